// round 3
// baseline (speedup 1.0000x reference)
#include <cuda_runtime.h>
#include <cuda_bf16.h>
#include <cstddef>
#include <cstdint>

#define BB 64
#define SSQ 2048
#define II 256
#define HH 256

// ---------------- scratch (device globals; allocation is forbidden) ----------------
__device__ float g_preA[33554432];   // 2048*64*256
__device__ float g_preB[33554432];   // 2048*64*256
__device__ float g_y0[67108864];     // 2048*64*512
__device__ unsigned g_cnt[64];       // [dir*32]
__device__ unsigned g_gen[64];       // [dir*32]

// ---------------- init: zero hn tail of output + reset barriers ----------------
__global__ void init_kernel(float* __restrict__ hn, int n) {
    int i = blockIdx.x * blockDim.x + threadIdx.x;
    if (i < n) hn[i] = 0.0f;
    if (blockIdx.x == 0 && threadIdx.x < 64) {
        g_cnt[threadIdx.x] = 0u;
        g_gen[threadIdx.x] = 0u;
    }
}

__global__ void reset_barrier_kernel() {
    if (threadIdx.x < 64) {
        g_cnt[threadIdx.x] = 0u;
        g_gen[threadIdx.x] = 0u;
    }
}

// ---------------- input-projection GEMM ----------------
// pre[m][n] = sum_k Arow(m)[k] * W[n][k] + bias[n],  m = s*64 + b
// MODE 0: Arow(m) = A + ((m&63)*2048 + (m>>6))*256   (A = x, K=256)
// MODE 1: Arow(m) = A + m*K                           (A = y0, K=512)
// grid.x = 4 (n-tiles: 0,1 -> fwd cols 0/128; 2,3 -> bwd cols 0/128), grid.y = 1024
template <int K, int MODE>
__global__ __launch_bounds__(256) void gemm_pre(
    const float* __restrict__ A,
    const float* __restrict__ Wf, const float* __restrict__ Wb,
    const float* __restrict__ bf, const float* __restrict__ bb,
    int ldw,
    float* __restrict__ outF, float* __restrict__ outB)
{
    __shared__ float As[16 * 132];
    __shared__ float Bs[16 * 132];

    const int tid = threadIdx.x;
    const int m0  = blockIdx.y * 128;
    const int nblk = blockIdx.x;
    const float* W    = (nblk < 2) ? Wf : Wb;
    const float* bias = (nblk < 2) ? bf : bb;
    float*       outp = (nblk < 2) ? outF : outB;
    const int n0 = (nblk & 1) * 128;

    const int lr  = tid >> 2;      // 0..63
    const int lc4 = tid & 3;       // 0..3

    const float *arow0, *arow1;
    {
        int ma = m0 + lr, mb = m0 + lr + 64;
        if (MODE == 0) {
            arow0 = A + ((size_t)(ma & 63) * SSQ + (size_t)(ma >> 6)) * II;
            arow1 = A + ((size_t)(mb & 63) * SSQ + (size_t)(mb >> 6)) * II;
        } else {
            arow0 = A + (size_t)ma * K;
            arow1 = A + (size_t)mb * K;
        }
    }
    const float* wrow0 = W + (size_t)(n0 + lr) * ldw;
    const float* wrow1 = W + (size_t)(n0 + lr + 64) * ldw;

    const int ty = tid >> 4;       // 0..15
    const int tx = tid & 15;       // 0..15

    float acc[8][8];
#pragma unroll
    for (int i = 0; i < 8; i++)
#pragma unroll
        for (int j = 0; j < 8; j++) acc[i][j] = 0.0f;

#pragma unroll 1
    for (int kt = 0; kt < K; kt += 16) {
        float4 a0 = *(const float4*)(arow0 + kt + lc4 * 4);
        float4 a1 = *(const float4*)(arow1 + kt + lc4 * 4);
        float4 w0 = *(const float4*)(wrow0 + kt + lc4 * 4);
        float4 w1 = *(const float4*)(wrow1 + kt + lc4 * 4);
        __syncthreads();
        As[(lc4 * 4 + 0) * 132 + lr] = a0.x;
        As[(lc4 * 4 + 1) * 132 + lr] = a0.y;
        As[(lc4 * 4 + 2) * 132 + lr] = a0.z;
        As[(lc4 * 4 + 3) * 132 + lr] = a0.w;
        As[(lc4 * 4 + 0) * 132 + lr + 64] = a1.x;
        As[(lc4 * 4 + 1) * 132 + lr + 64] = a1.y;
        As[(lc4 * 4 + 2) * 132 + lr + 64] = a1.z;
        As[(lc4 * 4 + 3) * 132 + lr + 64] = a1.w;
        Bs[(lc4 * 4 + 0) * 132 + lr] = w0.x;
        Bs[(lc4 * 4 + 1) * 132 + lr] = w0.y;
        Bs[(lc4 * 4 + 2) * 132 + lr] = w0.z;
        Bs[(lc4 * 4 + 3) * 132 + lr] = w0.w;
        Bs[(lc4 * 4 + 0) * 132 + lr + 64] = w1.x;
        Bs[(lc4 * 4 + 1) * 132 + lr + 64] = w1.y;
        Bs[(lc4 * 4 + 2) * 132 + lr + 64] = w1.z;
        Bs[(lc4 * 4 + 3) * 132 + lr + 64] = w1.w;
        __syncthreads();

#pragma unroll
        for (int kk = 0; kk < 16; kk++) {
            float af[8], bv[8];
            *(float4*)&af[0] = *(const float4*)&As[kk * 132 + ty * 8];
            *(float4*)&af[4] = *(const float4*)&As[kk * 132 + ty * 8 + 4];
            *(float4*)&bv[0] = *(const float4*)&Bs[kk * 132 + tx * 8];
            *(float4*)&bv[4] = *(const float4*)&Bs[kk * 132 + tx * 8 + 4];
#pragma unroll
            for (int i = 0; i < 8; i++)
#pragma unroll
                for (int j = 0; j < 8; j++)
                    acc[i][j] = fmaf(af[i], bv[j], acc[i][j]);
        }
    }

    float bj[8];
#pragma unroll
    for (int j = 0; j < 8; j++) bj[j] = bias[n0 + tx * 8 + j];

#pragma unroll
    for (int i = 0; i < 8; i++) {
        size_t m = (size_t)(m0 + ty * 8 + i);
        float4 v0 = make_float4(acc[i][0] + bj[0], acc[i][1] + bj[1],
                                acc[i][2] + bj[2], acc[i][3] + bj[3]);
        float4 v1 = make_float4(acc[i][4] + bj[4], acc[i][5] + bj[5],
                                acc[i][6] + bj[6], acc[i][7] + bj[7]);
        *(float4*)(outp + m * 256 + n0 + tx * 8)     = v0;
        *(float4*)(outp + m * 256 + n0 + tx * 8 + 4) = v1;
    }
}

// ---------------- persistent recurrent scan, both directions ----------------
// 128 blocks x 256 threads. dir = blockIdx.x>>6, nb = blockIdx.x&63 (4 hidden cols).
// thread = (b = tid>>2, kc = tid&3): K=256 split 4x64. Wh slice (4x256) in SMEM,
// h_prev slice (64 floats) in registers via __ldcg from the output buffer itself.
// Cross-block sync: per-direction accumulating barrier on L2 atomics.
__global__ __launch_bounds__(256, 1) void scan_kernel(
    const float* __restrict__ preF, const float* __restrict__ preB,
    const float* __restrict__ W_f, const float* __restrict__ W_b,
    int ldw, int whofs,
    float* __restrict__ out, size_t sS, size_t sB)
{
    __shared__ float WhS[4 * 256];

    const int tid = threadIdx.x;
    const int dir = blockIdx.x >> 6;
    const int nb  = blockIdx.x & 63;
    const int b   = tid >> 2;
    const int kc  = tid & 3;

    const float* pre = dir ? preB : preF;
    const float* W   = dir ? W_b  : W_f;
    const size_t dofs = (size_t)dir * 256;
    unsigned* cntp = &g_cnt[dir * 32];
    volatile unsigned* genp = (volatile unsigned*)&g_gen[dir * 32];

    // load Wh slice: rows nb*4 + (0..3), Wh columns 0..255 at offset whofs
    {
        int r = tid >> 6;             // 0..3
        int c = (tid & 63) * 4;       // 0..252
        const float* src = W + (size_t)(nb * 4 + r) * ldw + whofs + c;
        *(float4*)&WhS[r * 256 + c] = *(const float4*)src;
    }
    __syncthreads();

    const float* wbase = &WhS[kc * 64];
    float4 hv[16];

    for (int t = 0; t < 2048; ++t) {
        const int s = dir ? (2047 - t) : t;

        if (t == 0) {
#pragma unroll
            for (int j = 0; j < 16; j++) hv[j] = make_float4(0.f, 0.f, 0.f, 0.f);
        } else {
            const int sp = dir ? (s + 1) : (s - 1);
            const float4* hp = (const float4*)(out + (size_t)sp * sS +
                                               (size_t)b * sB + dofs + kc * 64);
#pragma unroll
            for (int j = 0; j < 16; j++) hv[j] = __ldcg(hp + j);
        }

        float acc0 = 0.f, acc1 = 0.f, acc2 = 0.f, acc3 = 0.f;
#pragma unroll
        for (int j = 0; j < 16; j++) {
            float4 h4 = hv[j];
            float4 wA = *(const float4*)(wbase + 0 * 256 + j * 4);
            float4 wB = *(const float4*)(wbase + 1 * 256 + j * 4);
            float4 wC = *(const float4*)(wbase + 2 * 256 + j * 4);
            float4 wD = *(const float4*)(wbase + 3 * 256 + j * 4);
            acc0 = fmaf(h4.x, wA.x, acc0); acc0 = fmaf(h4.y, wA.y, acc0);
            acc0 = fmaf(h4.z, wA.z, acc0); acc0 = fmaf(h4.w, wA.w, acc0);
            acc1 = fmaf(h4.x, wB.x, acc1); acc1 = fmaf(h4.y, wB.y, acc1);
            acc1 = fmaf(h4.z, wB.z, acc1); acc1 = fmaf(h4.w, wB.w, acc1);
            acc2 = fmaf(h4.x, wC.x, acc2); acc2 = fmaf(h4.y, wC.y, acc2);
            acc2 = fmaf(h4.z, wC.z, acc2); acc2 = fmaf(h4.w, wC.w, acc2);
            acc3 = fmaf(h4.x, wD.x, acc3); acc3 = fmaf(h4.y, wD.y, acc3);
            acc3 = fmaf(h4.z, wD.z, acc3); acc3 = fmaf(h4.w, wD.w, acc3);
        }

        // reduce over the 4 kc lanes (lane bits 0..1)
        acc0 += __shfl_xor_sync(0xffffffffu, acc0, 1);
        acc0 += __shfl_xor_sync(0xffffffffu, acc0, 2);
        acc1 += __shfl_xor_sync(0xffffffffu, acc1, 1);
        acc1 += __shfl_xor_sync(0xffffffffu, acc1, 2);
        acc2 += __shfl_xor_sync(0xffffffffu, acc2, 1);
        acc2 += __shfl_xor_sync(0xffffffffu, acc2, 2);
        acc3 += __shfl_xor_sync(0xffffffffu, acc3, 1);
        acc3 += __shfl_xor_sync(0xffffffffu, acc3, 2);

        float myacc = (kc == 0) ? acc0 : (kc == 1) ? acc1 : (kc == 2) ? acc2 : acc3;
        float p = __ldcg(pre + ((size_t)s * 64 + b) * 256 + nb * 4 + kc);
        float hnew = tanhf(p + myacc);
        __stcg(out + (size_t)s * sS + (size_t)b * sB + dofs + nb * 4 + kc, hnew);

        // ---- inter-block barrier for this direction ----
        __threadfence();
        __syncthreads();
        if (tid == 0) {
            unsigned target = (unsigned)(t + 1);
            unsigned old = atomicAdd(cntp, 1u);
            if (old + 1u == target * 64u) {
                atomicAdd((unsigned*)genp, 1u);
            } else {
                while (*genp < target) { }
            }
        }
        __syncthreads();
    }
}

// ---------------- launch ----------------
extern "C" void kernel_launch(void* const* d_in, const int* in_sizes, int n_in,
                              void* d_out, int out_size) {
    const float* x   = (const float*)d_in[0];
    const float* W0f = (const float*)d_in[1];
    const float* b0f = (const float*)d_in[2];
    const float* W0b = (const float*)d_in[3];
    const float* b0b = (const float*)d_in[4];
    const float* W1f = (const float*)d_in[5];
    const float* b1f = (const float*)d_in[6];
    const float* W1b = (const float*)d_in[7];
    const float* b1b = (const float*)d_in[8];
    float* out = (float*)d_out;

    float *preF, *preB, *y0;
    cudaGetSymbolAddress((void**)&preF, g_preA);
    cudaGetSymbolAddress((void**)&preB, g_preB);
    cudaGetSymbolAddress((void**)&y0,   g_y0);

    const size_t OUT_ELEMS = (size_t)BB * SSQ * 2 * HH;   // 67108864
    const int HN_ELEMS = 4 * BB * HH;                     // 65536

    // zero hn + reset barriers
    init_kernel<<<256, 256>>>(out + OUT_ELEMS, HN_ELEMS);

    // layer 0: pre = x @ Wx^T + b  (K=256, Wx = W0*[:, 0:256], ldw=512)
    gemm_pre<256, 0><<<dim3(4, 1024), 256>>>(x, W0f, W0b, b0f, b0b, 512, preF, preB);

    // layer 0 scan -> y0 [s][b][512] (fwd cols 0:256, bwd 256:512)
    scan_kernel<<<128, 256>>>(preF, preB, W0f, W0b, 512, 256,
                              y0, (size_t)BB * 512, (size_t)512);

    reset_barrier_kernel<<<1, 64>>>();

    // layer 1: pre = y0 @ Wx^T + b  (K=512, Wx = W1*[:, 0:512], ldw=768)
    gemm_pre<512, 1><<<dim3(4, 1024), 256>>>(y0, W1f, W1b, b1f, b1b, 768, preF, preB);

    // layer 1 scan -> out[b][s][512]
    scan_kernel<<<128, 256>>>(preF, preB, W1f, W1b, 768, 512,
                              out, (size_t)512, (size_t)SSQ * 512);
}

// round 4
// speedup vs baseline: 1.0163x; 1.0163x over previous
#include <cuda_runtime.h>
#include <cuda_bf16.h>
#include <cstddef>
#include <cstdint>

#define BB 64
#define SSQ 2048
#define II 256
#define HH 256

// ---------------- scratch (device globals; allocation is forbidden) ----------------
__device__ float g_preA[33554432];   // 2048*64*256
__device__ float g_preB[33554432];   // 2048*64*256
__device__ float g_y0[67108864];     // 2048*64*512
// per-block barrier flags: [dir][block] with 32-word (128B) stride
__device__ unsigned g_flags[2 * 64 * 32];

// ---------------- init: zero hn tail of output + reset barrier flags ----------------
__global__ void init_kernel(float* __restrict__ hn, int n) {
    int i = blockIdx.x * blockDim.x + threadIdx.x;
    if (i < n) hn[i] = 0.0f;
    if (i < 2 * 64 * 32) g_flags[i] = 0u;
}

// ---------------- input-projection GEMM ----------------
// pre[m][n] = sum_k Arow(m)[k] * W[n][k] + bias[n],  m = s*64 + b
// MODE 0: Arow(m) = A + ((m&63)*2048 + (m>>6))*256   (A = x, K=256)
// MODE 1: Arow(m) = A + m*K                           (A = y0, K=512)
// grid.x = 4 (n-tiles: 0,1 -> fwd cols 0/128; 2,3 -> bwd cols 0/128), grid.y = 1024
template <int K, int MODE>
__global__ __launch_bounds__(256) void gemm_pre(
    const float* __restrict__ A,
    const float* __restrict__ Wf, const float* __restrict__ Wb,
    const float* __restrict__ bf, const float* __restrict__ bb,
    int ldw,
    float* __restrict__ outF, float* __restrict__ outB)
{
    __shared__ float As[16 * 132];
    __shared__ float Bs[16 * 132];

    const int tid = threadIdx.x;
    const int m0  = blockIdx.y * 128;
    const int nblk = blockIdx.x;
    const float* W    = (nblk < 2) ? Wf : Wb;
    const float* bias = (nblk < 2) ? bf : bb;
    float*       outp = (nblk < 2) ? outF : outB;
    const int n0 = (nblk & 1) * 128;

    const int lr  = tid >> 2;      // 0..63
    const int lc4 = tid & 3;       // 0..3

    const float *arow0, *arow1;
    {
        int ma = m0 + lr, mb = m0 + lr + 64;
        if (MODE == 0) {
            arow0 = A + ((size_t)(ma & 63) * SSQ + (size_t)(ma >> 6)) * II;
            arow1 = A + ((size_t)(mb & 63) * SSQ + (size_t)(mb >> 6)) * II;
        } else {
            arow0 = A + (size_t)ma * K;
            arow1 = A + (size_t)mb * K;
        }
    }
    const float* wrow0 = W + (size_t)(n0 + lr) * ldw;
    const float* wrow1 = W + (size_t)(n0 + lr + 64) * ldw;

    const int ty = tid >> 4;       // 0..15
    const int tx = tid & 15;       // 0..15

    float acc[8][8];
#pragma unroll
    for (int i = 0; i < 8; i++)
#pragma unroll
        for (int j = 0; j < 8; j++) acc[i][j] = 0.0f;

#pragma unroll 1
    for (int kt = 0; kt < K; kt += 16) {
        float4 a0 = *(const float4*)(arow0 + kt + lc4 * 4);
        float4 a1 = *(const float4*)(arow1 + kt + lc4 * 4);
        float4 w0 = *(const float4*)(wrow0 + kt + lc4 * 4);
        float4 w1 = *(const float4*)(wrow1 + kt + lc4 * 4);
        __syncthreads();
        As[(lc4 * 4 + 0) * 132 + lr] = a0.x;
        As[(lc4 * 4 + 1) * 132 + lr] = a0.y;
        As[(lc4 * 4 + 2) * 132 + lr] = a0.z;
        As[(lc4 * 4 + 3) * 132 + lr] = a0.w;
        As[(lc4 * 4 + 0) * 132 + lr + 64] = a1.x;
        As[(lc4 * 4 + 1) * 132 + lr + 64] = a1.y;
        As[(lc4 * 4 + 2) * 132 + lr + 64] = a1.z;
        As[(lc4 * 4 + 3) * 132 + lr + 64] = a1.w;
        Bs[(lc4 * 4 + 0) * 132 + lr] = w0.x;
        Bs[(lc4 * 4 + 1) * 132 + lr] = w0.y;
        Bs[(lc4 * 4 + 2) * 132 + lr] = w0.z;
        Bs[(lc4 * 4 + 3) * 132 + lr] = w0.w;
        Bs[(lc4 * 4 + 0) * 132 + lr + 64] = w1.x;
        Bs[(lc4 * 4 + 1) * 132 + lr + 64] = w1.y;
        Bs[(lc4 * 4 + 2) * 132 + lr + 64] = w1.z;
        Bs[(lc4 * 4 + 3) * 132 + lr + 64] = w1.w;
        __syncthreads();

#pragma unroll
        for (int kk = 0; kk < 16; kk++) {
            float af[8], bv[8];
            *(float4*)&af[0] = *(const float4*)&As[kk * 132 + ty * 8];
            *(float4*)&af[4] = *(const float4*)&As[kk * 132 + ty * 8 + 4];
            *(float4*)&bv[0] = *(const float4*)&Bs[kk * 132 + tx * 8];
            *(float4*)&bv[4] = *(const float4*)&Bs[kk * 132 + tx * 8 + 4];
#pragma unroll
            for (int i = 0; i < 8; i++)
#pragma unroll
                for (int j = 0; j < 8; j++)
                    acc[i][j] = fmaf(af[i], bv[j], acc[i][j]);
        }
    }

    float bj[8];
#pragma unroll
    for (int j = 0; j < 8; j++) bj[j] = bias[n0 + tx * 8 + j];

#pragma unroll
    for (int i = 0; i < 8; i++) {
        size_t m = (size_t)(m0 + ty * 8 + i);
        float4 v0 = make_float4(acc[i][0] + bj[0], acc[i][1] + bj[1],
                                acc[i][2] + bj[2], acc[i][3] + bj[3]);
        float4 v1 = make_float4(acc[i][4] + bj[4], acc[i][5] + bj[5],
                                acc[i][6] + bj[6], acc[i][7] + bj[7]);
        *(float4*)(outp + m * 256 + n0 + tx * 8)     = v0;
        *(float4*)(outp + m * 256 + n0 + tx * 8 + 4) = v1;
    }
}

// ---------------- persistent recurrent scan, both directions ----------------
// 128 blocks x 256 threads. dir = blockIdx.x>>6, nb = blockIdx.x&63 (4 hidden cols).
// thread = (b = tid>>2, kc = tid&3): K=256 split 4x64. Wh slice (4x256) in SMEM,
// h_prev slice (64 floats) in registers via __ldcg from the previous timestep row.
// Cross-block sync: per-block release/acquire flag barrier (no atomics).
__global__ __launch_bounds__(256, 1) void scan_kernel(
    const float* __restrict__ preF, const float* __restrict__ preB,
    const float* __restrict__ W_f, const float* __restrict__ W_b,
    int ldw, int whofs,
    float* __restrict__ out, size_t sS, size_t sB, unsigned base)
{
    __shared__ float WhS[4 * 256];

    const int tid = threadIdx.x;
    const int dir = blockIdx.x >> 6;
    const int nb  = blockIdx.x & 63;
    const int b   = tid >> 2;
    const int kc  = tid & 3;

    const float* pre = dir ? preB : preF;
    const float* W   = dir ? W_b  : W_f;
    const size_t dofs = (size_t)dir * 256;
    unsigned* flags = &g_flags[dir * 64 * 32];
    unsigned* myflag = flags + nb * 32;
    unsigned* pollflag = flags + tid * 32;   // valid for tid < 64

    // load Wh slice: rows nb*4 + (0..3), Wh columns 0..255 at offset whofs
    {
        int r = tid >> 6;             // 0..3
        int c = (tid & 63) * 4;       // 0..252
        const float* src = W + (size_t)(nb * 4 + r) * ldw + whofs + c;
        *(float4*)&WhS[r * 256 + c] = *(const float4*)src;
    }
    __syncthreads();

    const float* wbase = &WhS[kc * 64];
    float4 hv[16];

    // prefetch pre for t = 0
    {
        const int s0 = dir ? 2047 : 0;
        // fallthrough into loop with p preloaded
    }
    int s = dir ? 2047 : 0;
    float p = __ldcg(pre + ((size_t)s * 64 + b) * 256 + nb * 4 + kc);

    for (int t = 0; t < 2048; ++t) {
        float acc0 = 0.f, acc1 = 0.f, acc2 = 0.f, acc3 = 0.f;

        if (t > 0) {
            const int sp = dir ? (s + 1) : (s - 1);
            const float4* hp = (const float4*)(out + (size_t)sp * sS +
                                               (size_t)b * sB + dofs + kc * 64);
#pragma unroll
            for (int j = 0; j < 16; j++) hv[j] = __ldcg(hp + j);

#pragma unroll
            for (int j = 0; j < 16; j++) {
                float4 h4 = hv[j];
                float4 wA = *(const float4*)(wbase + 0 * 256 + j * 4);
                float4 wB = *(const float4*)(wbase + 1 * 256 + j * 4);
                float4 wC = *(const float4*)(wbase + 2 * 256 + j * 4);
                float4 wD = *(const float4*)(wbase + 3 * 256 + j * 4);
                acc0 = fmaf(h4.x, wA.x, acc0); acc0 = fmaf(h4.y, wA.y, acc0);
                acc0 = fmaf(h4.z, wA.z, acc0); acc0 = fmaf(h4.w, wA.w, acc0);
                acc1 = fmaf(h4.x, wB.x, acc1); acc1 = fmaf(h4.y, wB.y, acc1);
                acc1 = fmaf(h4.z, wB.z, acc1); acc1 = fmaf(h4.w, wB.w, acc1);
                acc2 = fmaf(h4.x, wC.x, acc2); acc2 = fmaf(h4.y, wC.y, acc2);
                acc2 = fmaf(h4.z, wC.z, acc2); acc2 = fmaf(h4.w, wC.w, acc2);
                acc3 = fmaf(h4.x, wD.x, acc3); acc3 = fmaf(h4.y, wD.y, acc3);
                acc3 = fmaf(h4.z, wD.z, acc3); acc3 = fmaf(h4.w, wD.w, acc3);
            }

            // reduce over the 4 kc lanes (lane bits 0..1)
            acc0 += __shfl_xor_sync(0xffffffffu, acc0, 1);
            acc0 += __shfl_xor_sync(0xffffffffu, acc0, 2);
            acc1 += __shfl_xor_sync(0xffffffffu, acc1, 1);
            acc1 += __shfl_xor_sync(0xffffffffu, acc1, 2);
            acc2 += __shfl_xor_sync(0xffffffffu, acc2, 1);
            acc2 += __shfl_xor_sync(0xffffffffu, acc2, 2);
            acc3 += __shfl_xor_sync(0xffffffffu, acc3, 1);
            acc3 += __shfl_xor_sync(0xffffffffu, acc3, 2);
        }

        float myacc = (kc == 0) ? acc0 : (kc == 1) ? acc1 : (kc == 2) ? acc2 : acc3;
        float hnew = tanhf(p + myacc);
        __stcg(out + (size_t)s * sS + (size_t)b * sB + dofs + nb * 4 + kc, hnew);

        if (t == 2047) break;

        // ---- inter-block barrier for this direction (flag release/acquire) ----
        const unsigned target = base + (unsigned)(t + 1);
        __syncthreads();                       // all h stores issued (ordered by release below)
        if (tid == 0) {
            asm volatile("st.release.gpu.u32 [%0], %1;" :: "l"(myflag), "r"(target) : "memory");
        }

        // prefetch next pre while others arrive
        s = dir ? (s - 1) : (s + 1);
        p = __ldcg(pre + ((size_t)s * 64 + b) * 256 + nb * 4 + kc);

        if (tid < 64) {
            unsigned v;
            do {
                asm volatile("ld.acquire.gpu.u32 %0, [%1];" : "=r"(v) : "l"(pollflag) : "memory");
            } while (v < target);
        }
        __syncthreads();
    }
}

// ---------------- launch ----------------
extern "C" void kernel_launch(void* const* d_in, const int* in_sizes, int n_in,
                              void* d_out, int out_size) {
    const float* x   = (const float*)d_in[0];
    const float* W0f = (const float*)d_in[1];
    const float* b0f = (const float*)d_in[2];
    const float* W0b = (const float*)d_in[3];
    const float* b0b = (const float*)d_in[4];
    const float* W1f = (const float*)d_in[5];
    const float* b1f = (const float*)d_in[6];
    const float* W1b = (const float*)d_in[7];
    const float* b1b = (const float*)d_in[8];
    float* out = (float*)d_out;

    float *preF, *preB, *y0;
    cudaGetSymbolAddress((void**)&preF, g_preA);
    cudaGetSymbolAddress((void**)&preB, g_preB);
    cudaGetSymbolAddress((void**)&y0,   g_y0);

    const size_t OUT_ELEMS = (size_t)BB * SSQ * 2 * HH;   // 67108864
    const int HN_ELEMS = 4 * BB * HH;                     // 65536

    // zero hn + reset barrier flags (runs at the start of every replay)
    init_kernel<<<256, 256>>>(out + OUT_ELEMS, HN_ELEMS);

    // layer 0: pre = x @ Wx^T + b  (K=256, Wx = W0*[:, 0:256], ldw=512)
    gemm_pre<256, 0><<<dim3(4, 1024), 256>>>(x, W0f, W0b, b0f, b0b, 512, preF, preB);

    // layer 0 scan -> y0 [s][b][512] (fwd cols 0:256, bwd 256:512); flag targets 1..2047
    scan_kernel<<<128, 256>>>(preF, preB, W0f, W0b, 512, 256,
                              y0, (size_t)BB * 512, (size_t)512, 0u);

    // layer 1: pre = y0 @ Wx^T + b  (K=512, Wx = W1*[:, 0:512], ldw=768)
    gemm_pre<512, 1><<<dim3(4, 1024), 256>>>(y0, W1f, W1b, b1f, b1b, 768, preF, preB);

    // layer 1 scan -> out[b][s][512]; flag targets 2049..4095 (monotone, no reset needed)
    scan_kernel<<<128, 256>>>(preF, preB, W1f, W1b, 768, 512,
                              out, (size_t)512, (size_t)SSQ * 512, 2048u);
}

// round 5
// speedup vs baseline: 3.8212x; 3.7599x over previous
#include <cuda_runtime.h>
#include <cuda_bf16.h>
#include <cstddef>
#include <cstdint>

#define BB 64
#define SSQ 2048
#define II 256
#define HH 256

// ---------------- scratch (device globals; allocation is forbidden) ----------------
__device__ float g_preA[33554432];   // 2048*64*256
__device__ float g_preB[33554432];   // 2048*64*256
__device__ float g_y0[67108864];     // 2048*64*512

// ---------------- init: zero hn tail of output ----------------
__global__ void init_kernel(float* __restrict__ hn, int n) {
    int i = blockIdx.x * blockDim.x + threadIdx.x;
    if (i < n) hn[i] = 0.0f;
}

// ---------------- input-projection GEMM ----------------
// pre[m][n] = sum_k Arow(m)[k] * W[n][k] + bias[n],  m = s*64 + b
// MODE 0: Arow(m) = A + ((m&63)*2048 + (m>>6))*256   (A = x, K=256)
// MODE 1: Arow(m) = A + m*K                           (A = y0, K=512)
// grid.x = 4 (n-tiles: 0,1 -> fwd cols 0/128; 2,3 -> bwd cols 0/128), grid.y = 1024
template <int K, int MODE>
__global__ __launch_bounds__(256, 2) void gemm_pre(
    const float* __restrict__ A,
    const float* __restrict__ Wf, const float* __restrict__ Wb,
    const float* __restrict__ bf, const float* __restrict__ bb,
    int ldw,
    float* __restrict__ outF, float* __restrict__ outB)
{
    __shared__ float As[16 * 132];
    __shared__ float Bs[16 * 132];

    const int tid = threadIdx.x;
    const int m0  = blockIdx.y * 128;
    const int nblk = blockIdx.x;
    const float* W    = (nblk < 2) ? Wf : Wb;
    const float* bias = (nblk < 2) ? bf : bb;
    float*       outp = (nblk < 2) ? outF : outB;
    const int n0 = (nblk & 1) * 128;

    const int lr  = tid >> 2;      // 0..63
    const int lc4 = tid & 3;       // 0..3

    const float *arow0, *arow1;
    {
        int ma = m0 + lr, mb = m0 + lr + 64;
        if (MODE == 0) {
            arow0 = A + ((size_t)(ma & 63) * SSQ + (size_t)(ma >> 6)) * II;
            arow1 = A + ((size_t)(mb & 63) * SSQ + (size_t)(mb >> 6)) * II;
        } else {
            arow0 = A + (size_t)ma * K;
            arow1 = A + (size_t)mb * K;
        }
    }
    const float* wrow0 = W + (size_t)(n0 + lr) * ldw;
    const float* wrow1 = W + (size_t)(n0 + lr + 64) * ldw;

    const int ty = tid >> 4;       // 0..15
    const int tx = tid & 15;       // 0..15

    float acc[8][8];
#pragma unroll
    for (int i = 0; i < 8; i++)
#pragma unroll
        for (int j = 0; j < 8; j++) acc[i][j] = 0.0f;

#pragma unroll 1
    for (int kt = 0; kt < K; kt += 16) {
        float4 a0 = *(const float4*)(arow0 + kt + lc4 * 4);
        float4 a1 = *(const float4*)(arow1 + kt + lc4 * 4);
        float4 w0 = *(const float4*)(wrow0 + kt + lc4 * 4);
        float4 w1 = *(const float4*)(wrow1 + kt + lc4 * 4);
        __syncthreads();
        As[(lc4 * 4 + 0) * 132 + lr] = a0.x;
        As[(lc4 * 4 + 1) * 132 + lr] = a0.y;
        As[(lc4 * 4 + 2) * 132 + lr] = a0.z;
        As[(lc4 * 4 + 3) * 132 + lr] = a0.w;
        As[(lc4 * 4 + 0) * 132 + lr + 64] = a1.x;
        As[(lc4 * 4 + 1) * 132 + lr + 64] = a1.y;
        As[(lc4 * 4 + 2) * 132 + lr + 64] = a1.z;
        As[(lc4 * 4 + 3) * 132 + lr + 64] = a1.w;
        Bs[(lc4 * 4 + 0) * 132 + lr] = w0.x;
        Bs[(lc4 * 4 + 1) * 132 + lr] = w0.y;
        Bs[(lc4 * 4 + 2) * 132 + lr] = w0.z;
        Bs[(lc4 * 4 + 3) * 132 + lr] = w0.w;
        Bs[(lc4 * 4 + 0) * 132 + lr + 64] = w1.x;
        Bs[(lc4 * 4 + 1) * 132 + lr + 64] = w1.y;
        Bs[(lc4 * 4 + 2) * 132 + lr + 64] = w1.z;
        Bs[(lc4 * 4 + 3) * 132 + lr + 64] = w1.w;
        __syncthreads();

#pragma unroll
        for (int kk = 0; kk < 16; kk++) {
            float af[8], bv[8];
            *(float4*)&af[0] = *(const float4*)&As[kk * 132 + ty * 8];
            *(float4*)&af[4] = *(const float4*)&As[kk * 132 + ty * 8 + 4];
            *(float4*)&bv[0] = *(const float4*)&Bs[kk * 132 + tx * 8];
            *(float4*)&bv[4] = *(const float4*)&Bs[kk * 132 + tx * 8 + 4];
#pragma unroll
            for (int i = 0; i < 8; i++)
#pragma unroll
                for (int j = 0; j < 8; j++)
                    acc[i][j] = fmaf(af[i], bv[j], acc[i][j]);
        }
    }

    float bj[8];
#pragma unroll
    for (int j = 0; j < 8; j++) bj[j] = bias[n0 + tx * 8 + j];

#pragma unroll
    for (int i = 0; i < 8; i++) {
        size_t m = (size_t)(m0 + ty * 8 + i);
        float4 v0 = make_float4(acc[i][0] + bj[0], acc[i][1] + bj[1],
                                acc[i][2] + bj[2], acc[i][3] + bj[3]);
        float4 v1 = make_float4(acc[i][4] + bj[4], acc[i][5] + bj[5],
                                acc[i][6] + bj[6], acc[i][7] + bj[7]);
        *(float4*)(outp + m * 256 + n0 + tx * 8)     = v0;
        *(float4*)(outp + m * 256 + n0 + tx * 8 + 4) = v1;
    }
}

// ---------------- batch-parallel recurrent scan (cluster of 2) ----------------
// 128 CTAs x 512 threads, clusters of 2. Cluster cl handles 2 recurrences:
// dir = cl>>5, batches bpair = (cl&31)*2 + {0,1}.
// CTA rank r owns output columns [r*128, r*128+128) and holds its half of Wh
// ENTIRELY IN REGISTERS: thread (kq=tid&3, o=tid>>2) holds Wh[r*128+o][kq*64 .. +64).
// Per step: read h(t-1) (both recs) from SMEM, 128 FFMA/thread, shfl-reduce over
// kq lanes, exchange new half-h with peer CTA via st.shared::cluster + cluster barrier.
// SMEM h layout: [parity][rec][4 blocks of 64 @ stride 68] -> conflict-free LDS.128.
__global__ __launch_bounds__(512, 1) __cluster_dims__(2, 1, 1)
void scan2(const float* __restrict__ preF, const float* __restrict__ preB,
           const float* __restrict__ W_f, const float* __restrict__ W_b,
           int ldw, int whofs,
           float* __restrict__ out, size_t sS, size_t sB)
{
    __shared__ float hb[2 * 2 * 272];   // [parity][rec][272]

    const int tid = threadIdx.x;
    const int kq  = tid & 3;
    const int o   = tid >> 2;          // 0..127
    uint32_t r;
    asm("mov.u32 %0, %%cluster_ctarank;" : "=r"(r));
    const int cl    = blockIdx.x >> 1;
    const int dir   = cl >> 5;
    const int bpair = (cl & 31) * 2;
    const int colg  = (int)r * 128 + o;

    const float* pre = dir ? preB : preF;
    const float* W   = dir ? W_b : W_f;

    // load my 64 weights into registers (once)
    float4 wreg[16];
    {
        const float* wp = W + (size_t)colg * ldw + whofs + kq * 64;
#pragma unroll
        for (int i = 0; i < 16; i++) wreg[i] = *(const float4*)(wp + i * 4);
    }

    const bool active = (kq < 2);          // lanes that own a (rec, col) output
    const int  myb    = bpair + kq;        // batch for my rec (valid if active)

    uint32_t hb_base;
    asm("{ .reg .u64 t; cvta.to.shared.u64 t, %1; cvt.u32.u64 %0, t; }"
        : "=r"(hb_base) : "l"(hb));

    int s = dir ? 2047 : 0;
    const int sstep = dir ? -1 : 1;

    float pval = 0.f;
    if (active) pval = __ldg(pre + ((size_t)s * 64 + myb) * 256 + colg);

    int par = 0;
    for (int t = 0; t < 2048; ++t) {
        float sum0 = 0.f, sum1 = 0.f;
        if (t > 0) {
            float a00 = 0.f, a01 = 0.f, a02 = 0.f, a03 = 0.f;
            float a10 = 0.f, a11 = 0.f, a12 = 0.f, a13 = 0.f;
            const float* h0 = &hb[par * 544 + 0 * 272 + kq * 68];
            const float* h1 = &hb[par * 544 + 1 * 272 + kq * 68];
#pragma unroll
            for (int i = 0; i < 16; i++) {
                float4 h = *(const float4*)(h0 + i * 4);
                a00 = fmaf(wreg[i].x, h.x, a00);
                a01 = fmaf(wreg[i].y, h.y, a01);
                a02 = fmaf(wreg[i].z, h.z, a02);
                a03 = fmaf(wreg[i].w, h.w, a03);
            }
#pragma unroll
            for (int i = 0; i < 16; i++) {
                float4 h = *(const float4*)(h1 + i * 4);
                a10 = fmaf(wreg[i].x, h.x, a10);
                a11 = fmaf(wreg[i].y, h.y, a11);
                a12 = fmaf(wreg[i].z, h.z, a12);
                a13 = fmaf(wreg[i].w, h.w, a13);
            }
            sum0 = (a00 + a01) + (a02 + a03);
            sum1 = (a10 + a11) + (a12 + a13);
            // reduce over the 4 kq lanes (lane bits 0,1)
            sum0 += __shfl_xor_sync(0xffffffffu, sum0, 1);
            sum0 += __shfl_xor_sync(0xffffffffu, sum0, 2);
            sum1 += __shfl_xor_sync(0xffffffffu, sum1, 1);
            sum1 += __shfl_xor_sync(0xffffffffu, sum1, 2);
        }

        float hnew = 0.f;
        if (active) {
            float acc = (kq == 0) ? sum0 : sum1;
            hnew = tanhf(pval + acc);
            out[(size_t)s * sS + (size_t)myb * sB + (size_t)dir * 256 + colg] = hnew;
        }
        if (t == 2047) break;

        const int np = par ^ 1;
        if (active) {
            // own SMEM h buffer
            const int hidx = np * 544 + kq * 272 + (colg >> 6) * 68 + (colg & 63);
            hb[hidx] = hnew;
            // peer CTA's h buffer (other half provider)
            uint32_t laddr = hb_base + (uint32_t)hidx * 4u;
            uint32_t raddr;
            asm("mapa.shared::cluster.u32 %0, %1, %2;"
                : "=r"(raddr) : "r"(laddr), "r"(r ^ 1u));
            asm volatile("st.shared::cluster.f32 [%0], %1;"
                         :: "r"(raddr), "f"(hnew) : "memory");
        }

        // prefetch next pre while the exchange settles
        s += sstep;
        if (active) pval = __ldg(pre + ((size_t)s * 64 + myb) * 256 + colg);

        asm volatile("barrier.cluster.arrive.aligned;" ::: "memory");
        asm volatile("barrier.cluster.wait.aligned;" ::: "memory");
        par = np;
    }
}

// ---------------- launch ----------------
extern "C" void kernel_launch(void* const* d_in, const int* in_sizes, int n_in,
                              void* d_out, int out_size) {
    const float* x   = (const float*)d_in[0];
    const float* W0f = (const float*)d_in[1];
    const float* b0f = (const float*)d_in[2];
    const float* W0b = (const float*)d_in[3];
    const float* b0b = (const float*)d_in[4];
    const float* W1f = (const float*)d_in[5];
    const float* b1f = (const float*)d_in[6];
    const float* W1b = (const float*)d_in[7];
    const float* b1b = (const float*)d_in[8];
    float* out = (float*)d_out;

    float *preF, *preB, *y0;
    cudaGetSymbolAddress((void**)&preF, g_preA);
    cudaGetSymbolAddress((void**)&preB, g_preB);
    cudaGetSymbolAddress((void**)&y0,   g_y0);

    const size_t OUT_ELEMS = (size_t)BB * SSQ * 2 * HH;   // 67108864
    const int HN_ELEMS = 4 * BB * HH;                     // 65536

    // zero hn
    init_kernel<<<256, 256>>>(out + OUT_ELEMS, HN_ELEMS);

    // layer 0: pre = x @ Wx^T + b  (K=256, Wx = W0*[:, 0:256], ldw=512)
    gemm_pre<256, 0><<<dim3(4, 1024), 256>>>(x, W0f, W0b, b0f, b0b, 512, preF, preB);

    // layer 0 scan -> y0 [s][b][512] (fwd cols 0:256, bwd 256:512)
    scan2<<<128, 512>>>(preF, preB, W0f, W0b, 512, 256,
                        y0, (size_t)BB * 512, (size_t)512);

    // layer 1: pre = y0 @ Wx^T + b  (K=512, Wx = W1*[:, 0:512], ldw=768)
    gemm_pre<512, 1><<<dim3(4, 1024), 256>>>(y0, W1f, W1b, b1f, b1b, 768, preF, preB);

    // layer 1 scan -> out[b][s][512]
    scan2<<<128, 512>>>(preF, preB, W1f, W1b, 768, 512,
                        out, (size_t)512, (size_t)SSQ * 512);
}

// round 6
// speedup vs baseline: 3.9621x; 1.0369x over previous
#include <cuda_runtime.h>
#include <cuda_bf16.h>
#include <cstddef>
#include <cstdint>

#define BB 64
#define SSQ 2048
#define II 256
#define HH 256

// ---------------- scratch (device globals; allocation is forbidden) ----------------
__device__ float g_preA[33554432];   // 2048*64*256
__device__ float g_preB[33554432];   // 2048*64*256
__device__ float g_y0[67108864];     // 2048*64*512

// ---------------- init: zero hn tail of output ----------------
__global__ void init_kernel(float* __restrict__ hn, int n) {
    int i = blockIdx.x * blockDim.x + threadIdx.x;
    if (i < n) hn[i] = 0.0f;
}

// ---------------- input-projection GEMM ----------------
// pre[m][n] = sum_k Arow(m)[k] * W[n][k] + bias[n],  m = s*64 + b
// MODE 0: Arow(m) = A + ((m&63)*2048 + (m>>6))*256   (A = x, K=256)
// MODE 1: Arow(m) = A + m*K                           (A = y0, K=512)
// grid.x = 4 (n-tiles: 0,1 -> fwd cols 0/128; 2,3 -> bwd cols 0/128), grid.y = 1024
// Register double-buffer: LDGs for tile kt+16 are issued BEFORE computing tile kt,
// so global latency is hidden behind the ~4K-cycle compute phase.
template <int K, int MODE>
__global__ __launch_bounds__(256, 2) void gemm_pre(
    const float* __restrict__ A,
    const float* __restrict__ Wf, const float* __restrict__ Wb,
    const float* __restrict__ bf, const float* __restrict__ bb,
    int ldw,
    float* __restrict__ outF, float* __restrict__ outB)
{
    __shared__ float As[16 * 132];
    __shared__ float Bs[16 * 132];

    const int tid = threadIdx.x;
    const int m0  = blockIdx.y * 128;
    const int nblk = blockIdx.x;
    const float* W    = (nblk < 2) ? Wf : Wb;
    const float* bias = (nblk < 2) ? bf : bb;
    float*       outp = (nblk < 2) ? outF : outB;
    const int n0 = (nblk & 1) * 128;

    const int lr  = tid >> 2;      // 0..63
    const int lc4 = tid & 3;       // 0..3

    const float *arow0, *arow1;
    {
        int ma = m0 + lr, mb = m0 + lr + 64;
        if (MODE == 0) {
            arow0 = A + ((size_t)(ma & 63) * SSQ + (size_t)(ma >> 6)) * II;
            arow1 = A + ((size_t)(mb & 63) * SSQ + (size_t)(mb >> 6)) * II;
        } else {
            arow0 = A + (size_t)ma * K;
            arow1 = A + (size_t)mb * K;
        }
    }
    const float* wrow0 = W + (size_t)(n0 + lr) * ldw;
    const float* wrow1 = W + (size_t)(n0 + lr + 64) * ldw;

    const int ty = tid >> 4;       // 0..15
    const int tx = tid & 15;       // 0..15

    float acc[8][8];
#pragma unroll
    for (int i = 0; i < 8; i++)
#pragma unroll
        for (int j = 0; j < 8; j++) acc[i][j] = 0.0f;

    // prologue: loads for tile 0
    float4 a0 = *(const float4*)(arow0 + lc4 * 4);
    float4 a1 = *(const float4*)(arow1 + lc4 * 4);
    float4 w0 = *(const float4*)(wrow0 + lc4 * 4);
    float4 w1 = *(const float4*)(wrow1 + lc4 * 4);

#pragma unroll 1
    for (int kt = 0; kt < K; kt += 16) {
        __syncthreads();   // previous tile fully consumed
        As[(lc4 * 4 + 0) * 132 + lr] = a0.x;
        As[(lc4 * 4 + 1) * 132 + lr] = a0.y;
        As[(lc4 * 4 + 2) * 132 + lr] = a0.z;
        As[(lc4 * 4 + 3) * 132 + lr] = a0.w;
        As[(lc4 * 4 + 0) * 132 + lr + 64] = a1.x;
        As[(lc4 * 4 + 1) * 132 + lr + 64] = a1.y;
        As[(lc4 * 4 + 2) * 132 + lr + 64] = a1.z;
        As[(lc4 * 4 + 3) * 132 + lr + 64] = a1.w;
        Bs[(lc4 * 4 + 0) * 132 + lr] = w0.x;
        Bs[(lc4 * 4 + 1) * 132 + lr] = w0.y;
        Bs[(lc4 * 4 + 2) * 132 + lr] = w0.z;
        Bs[(lc4 * 4 + 3) * 132 + lr] = w0.w;
        Bs[(lc4 * 4 + 0) * 132 + lr + 64] = w1.x;
        Bs[(lc4 * 4 + 1) * 132 + lr + 64] = w1.y;
        Bs[(lc4 * 4 + 2) * 132 + lr + 64] = w1.z;
        Bs[(lc4 * 4 + 3) * 132 + lr + 64] = w1.w;
        __syncthreads();

        // issue next tile's loads; consumed only after this tile's compute
        if (kt + 16 < K) {
            a0 = *(const float4*)(arow0 + kt + 16 + lc4 * 4);
            a1 = *(const float4*)(arow1 + kt + 16 + lc4 * 4);
            w0 = *(const float4*)(wrow0 + kt + 16 + lc4 * 4);
            w1 = *(const float4*)(wrow1 + kt + 16 + lc4 * 4);
        }

#pragma unroll
        for (int kk = 0; kk < 16; kk++) {
            float af[8], bv[8];
            *(float4*)&af[0] = *(const float4*)&As[kk * 132 + ty * 8];
            *(float4*)&af[4] = *(const float4*)&As[kk * 132 + ty * 8 + 4];
            *(float4*)&bv[0] = *(const float4*)&Bs[kk * 132 + tx * 8];
            *(float4*)&bv[4] = *(const float4*)&Bs[kk * 132 + tx * 8 + 4];
#pragma unroll
            for (int i = 0; i < 8; i++)
#pragma unroll
                for (int j = 0; j < 8; j++)
                    acc[i][j] = fmaf(af[i], bv[j], acc[i][j]);
        }
    }

    float bj[8];
#pragma unroll
    for (int j = 0; j < 8; j++) bj[j] = bias[n0 + tx * 8 + j];

#pragma unroll
    for (int i = 0; i < 8; i++) {
        size_t m = (size_t)(m0 + ty * 8 + i);
        float4 v0 = make_float4(acc[i][0] + bj[0], acc[i][1] + bj[1],
                                acc[i][2] + bj[2], acc[i][3] + bj[3]);
        float4 v1 = make_float4(acc[i][4] + bj[4], acc[i][5] + bj[5],
                                acc[i][6] + bj[6], acc[i][7] + bj[7]);
        *(float4*)(outp + m * 256 + n0 + tx * 8)     = v0;
        *(float4*)(outp + m * 256 + n0 + tx * 8 + 4) = v1;
    }
}

// ---------------- batch-parallel recurrent scan (cluster of 2) ----------------
// 128 CTAs x 512 threads, clusters of 2. Cluster cl handles 2 recurrences:
// dir = cl>>5, batches bpair = (cl&31)*2 + {0,1}.
// CTA rank r owns output columns [r*128, r*128+128) and holds its half of Wh
// ENTIRELY IN REGISTERS. Per step: h(t-1) from SMEM, 128 FFMA/thread, shfl-reduce,
// exchange new half-h with peer via st.shared::cluster; arrive EARLY, then overlap
// global out-store + pre prefetch with the cluster barrier, then wait.
__global__ __launch_bounds__(512, 1) __cluster_dims__(2, 1, 1)
void scan2(const float* __restrict__ preF, const float* __restrict__ preB,
           const float* __restrict__ W_f, const float* __restrict__ W_b,
           int ldw, int whofs,
           float* __restrict__ out, size_t sS, size_t sB)
{
    __shared__ float hb[2 * 2 * 272];   // [parity][rec][272]

    const int tid = threadIdx.x;
    const int kq  = tid & 3;
    const int o   = tid >> 2;          // 0..127
    uint32_t r;
    asm("mov.u32 %0, %%cluster_ctarank;" : "=r"(r));
    const int cl    = blockIdx.x >> 1;
    const int dir   = cl >> 5;
    const int bpair = (cl & 31) * 2;
    const int colg  = (int)r * 128 + o;

    const float* pre = dir ? preB : preF;
    const float* W   = dir ? W_b : W_f;

    // load my 64 weights into registers (once)
    float4 wreg[16];
    {
        const float* wp = W + (size_t)colg * ldw + whofs + kq * 64;
#pragma unroll
        for (int i = 0; i < 16; i++) wreg[i] = *(const float4*)(wp + i * 4);
    }

    const bool active = (kq < 2);          // lanes that own a (rec, col) output
    const int  myb    = bpair + kq;        // batch for my rec (valid if active)

    uint32_t hb_base;
    asm("{ .reg .u64 t; cvta.to.shared.u64 t, %1; cvt.u32.u64 %0, t; }"
        : "=r"(hb_base) : "l"(hb));

    // precompute peer address for my h slot (both parities)
    const int hidx0 = 0 * 544 + kq * 272 + (colg >> 6) * 68 + (colg & 63);
    uint32_t raddr0 = 0;
    if (active) {
        uint32_t laddr = hb_base + (uint32_t)hidx0 * 4u;
        asm("mapa.shared::cluster.u32 %0, %1, %2;"
            : "=r"(raddr0) : "r"(laddr), "r"(r ^ 1u));
    }

    int s = dir ? 2047 : 0;
    const int sstep = dir ? -1 : 1;

    float pval = 0.f;
    if (active) pval = __ldg(pre + ((size_t)s * 64 + myb) * 256 + colg);

    float* outp = out + (size_t)myb * sB + (size_t)dir * 256 + colg;

    int par = 0;
    for (int t = 0; t < 2048; ++t) {
        float sum0 = 0.f, sum1 = 0.f;
        if (t > 0) {
            float a00 = 0.f, a01 = 0.f, a02 = 0.f, a03 = 0.f;
            float a10 = 0.f, a11 = 0.f, a12 = 0.f, a13 = 0.f;
            const float* h0 = &hb[par * 544 + 0 * 272 + kq * 68];
            const float* h1 = &hb[par * 544 + 1 * 272 + kq * 68];
#pragma unroll
            for (int i = 0; i < 16; i++) {
                float4 h = *(const float4*)(h0 + i * 4);
                a00 = fmaf(wreg[i].x, h.x, a00);
                a01 = fmaf(wreg[i].y, h.y, a01);
                a02 = fmaf(wreg[i].z, h.z, a02);
                a03 = fmaf(wreg[i].w, h.w, a03);
            }
#pragma unroll
            for (int i = 0; i < 16; i++) {
                float4 h = *(const float4*)(h1 + i * 4);
                a10 = fmaf(wreg[i].x, h.x, a10);
                a11 = fmaf(wreg[i].y, h.y, a11);
                a12 = fmaf(wreg[i].z, h.z, a12);
                a13 = fmaf(wreg[i].w, h.w, a13);
            }
            sum0 = (a00 + a01) + (a02 + a03);
            sum1 = (a10 + a11) + (a12 + a13);
            // reduce over the 4 kq lanes (lane bits 0,1)
            sum0 += __shfl_xor_sync(0xffffffffu, sum0, 1);
            sum0 += __shfl_xor_sync(0xffffffffu, sum0, 2);
            sum1 += __shfl_xor_sync(0xffffffffu, sum1, 1);
            sum1 += __shfl_xor_sync(0xffffffffu, sum1, 2);
        }

        float hnew = 0.f;
        if (active) {
            float acc = (kq == 0) ? sum0 : sum1;
            hnew = tanhf(pval + acc);
        }

        if (t < 2047) {
            const int np = par ^ 1;
            if (active) {
                const int hidx = np * 544 + hidx0;
                hb[hidx] = hnew;                        // own buffer
                uint32_t raddr = raddr0 + (uint32_t)(np * 544) * 4u;
                asm volatile("st.shared::cluster.f32 [%0], %1;"
                             :: "r"(raddr), "f"(hnew) : "memory");
            }
            // release: prior (cluster-)shared stores visible to peer after its wait
            asm volatile("barrier.cluster.arrive.aligned;" ::: "memory");

            // overlap with barrier: global out store + next pre prefetch
            if (active) __stcg(outp + (size_t)s * sS, hnew);
            s += sstep;
            if (active) pval = __ldg(pre + ((size_t)s * 64 + myb) * 256 + colg);

            asm volatile("barrier.cluster.wait.aligned;" ::: "memory");
            par = np;
        } else {
            if (active) __stcg(outp + (size_t)s * sS, hnew);
        }
    }
}

// ---------------- launch ----------------
extern "C" void kernel_launch(void* const* d_in, const int* in_sizes, int n_in,
                              void* d_out, int out_size) {
    const float* x   = (const float*)d_in[0];
    const float* W0f = (const float*)d_in[1];
    const float* b0f = (const float*)d_in[2];
    const float* W0b = (const float*)d_in[3];
    const float* b0b = (const float*)d_in[4];
    const float* W1f = (const float*)d_in[5];
    const float* b1f = (const float*)d_in[6];
    const float* W1b = (const float*)d_in[7];
    const float* b1b = (const float*)d_in[8];
    float* out = (float*)d_out;

    float *preF, *preB, *y0;
    cudaGetSymbolAddress((void**)&preF, g_preA);
    cudaGetSymbolAddress((void**)&preB, g_preB);
    cudaGetSymbolAddress((void**)&y0,   g_y0);

    const size_t OUT_ELEMS = (size_t)BB * SSQ * 2 * HH;   // 67108864
    const int HN_ELEMS = 4 * BB * HH;                     // 65536

    // zero hn
    init_kernel<<<256, 256>>>(out + OUT_ELEMS, HN_ELEMS);

    // layer 0: pre = x @ Wx^T + b  (K=256, Wx = W0*[:, 0:256], ldw=512)
    gemm_pre<256, 0><<<dim3(4, 1024), 256>>>(x, W0f, W0b, b0f, b0b, 512, preF, preB);

    // layer 0 scan -> y0 [s][b][512] (fwd cols 0:256, bwd 256:512)
    scan2<<<128, 512>>>(preF, preB, W0f, W0b, 512, 256,
                        y0, (size_t)BB * 512, (size_t)512);

    // layer 1: pre = y0 @ Wx^T + b  (K=512, Wx = W1*[:, 0:512], ldw=768)
    gemm_pre<512, 1><<<dim3(4, 1024), 256>>>(y0, W1f, W1b, b1f, b1b, 768, preF, preB);

    // layer 1 scan -> out[b][s][512]
    scan2<<<128, 512>>>(preF, preB, W1f, W1b, 768, 512,
                        out, (size_t)512, (size_t)SSQ * 512);
}

// round 8
// speedup vs baseline: 4.4405x; 1.1208x over previous
#include <cuda_runtime.h>
#include <cuda_bf16.h>
#include <cstddef>
#include <cstdint>

#define BB 64
#define SSQ 2048
#define II 256
#define HH 256

// ---------------- scratch (device globals; allocation is forbidden) ----------------
__device__ float g_preA[33554432];   // 2048*64*256
__device__ float g_preB[33554432];   // 2048*64*256
__device__ float g_y0[67108864];     // 2048*64*512

// ---------------- init: zero hn tail of output ----------------
__global__ void init_kernel(float* __restrict__ hn, int n) {
    int i = blockIdx.x * blockDim.x + threadIdx.x;
    if (i < n) hn[i] = 0.0f;
}

// ---------------- helpers ----------------
__device__ __forceinline__ uint32_t smem_u32(const void* p) {
    uint32_t a;
    asm("{ .reg .u64 t; cvta.to.shared.u64 t, %1; cvt.u32.u64 %0, t; }"
        : "=r"(a) : "l"(p));
    return a;
}

// float4 -> packed bf16 hi pair/lo pair (hi = rn(x), lo = rn(x - hi))
__device__ __forceinline__ void split_f4(float4 f, uint32_t& h01, uint32_t& h23,
                                         uint32_t& l01, uint32_t& l23) {
    asm("cvt.rn.bf16x2.f32 %0, %1, %2;" : "=r"(h01) : "f"(f.y), "f"(f.x));
    asm("cvt.rn.bf16x2.f32 %0, %1, %2;" : "=r"(h23) : "f"(f.w), "f"(f.z));
    float h0 = __uint_as_float(h01 << 16);
    float h1 = __uint_as_float(h01 & 0xffff0000u);
    float h2 = __uint_as_float(h23 << 16);
    float h3 = __uint_as_float(h23 & 0xffff0000u);
    float l0 = f.x - h0, l1 = f.y - h1, l2 = f.z - h2, l3 = f.w - h3;
    asm("cvt.rn.bf16x2.f32 %0, %1, %2;" : "=r"(l01) : "f"(l1), "f"(l0));
    asm("cvt.rn.bf16x2.f32 %0, %1, %2;" : "=r"(l23) : "f"(l3), "f"(l2));
}

__device__ __forceinline__ void sts_v2(uint32_t addr, uint32_t a, uint32_t b) {
    asm volatile("st.shared.v2.b32 [%0], {%1, %2};" :: "r"(addr), "r"(a), "r"(b)
                 : "memory");
}

__device__ __forceinline__ void ldsm_x4(uint32_t addr, uint32_t& r0, uint32_t& r1,
                                        uint32_t& r2, uint32_t& r3) {
    asm volatile("ldmatrix.sync.aligned.m8n8.x4.shared.b16 {%0,%1,%2,%3}, [%4];"
                 : "=r"(r0), "=r"(r1), "=r"(r2), "=r"(r3) : "r"(addr));
}

__device__ __forceinline__ void mma16816(float* c, const uint32_t* a,
                                         const uint32_t* b) {
    asm volatile(
        "mma.sync.aligned.m16n8k16.row.col.f32.bf16.bf16.f32 "
        "{%0,%1,%2,%3}, {%4,%5,%6,%7}, {%8,%9}, {%0,%1,%2,%3};"
        : "+f"(c[0]), "+f"(c[1]), "+f"(c[2]), "+f"(c[3])
        : "r"(a[0]), "r"(a[1]), "r"(a[2]), "r"(a[3]), "r"(b[0]), "r"(b[1]));
}

// ---------------- tensor-core (HMMA mma.sync) input-projection GEMM ----------------
// pre[m][n] = sum_k Arow(m)[k] * W[n][k] + bias[n],  m = s*64 + b
// bf16 hi/lo split: D = AhiBhi + AhiBlo + AloBhi (fp32 accum) ~ 1e-5 rel err.
// CTA: 128(M) x 128(N), BK=32; 8 warps = 2(M) x 4(N), warp tile 64x32.
// SMEM tiles Ahi/Alo/Whi/Wlo: 128 rows x 32 bf16, padded row stride 80 B
// (5x16B -> conflict-free ldmatrix). Register-prefetch of next fp32 chunk.
// MODE 0: Arow(m) = x + ((m&63)*2048 + (m>>6))*256 ; MODE 1: Arow(m) = A + m*K
// grid.x = 4 (n-tiles: 0,1 -> fwd n0 0/128; 2,3 -> bwd), grid.y = M/128.
template <int K, int MODE>
__global__ __launch_bounds__(256) void gemm_pre_mma(
    const float* __restrict__ A,
    const float* __restrict__ Wf, const float* __restrict__ Wb,
    const float* __restrict__ bf, const float* __restrict__ bb,
    int ldw,
    float* __restrict__ outF, float* __restrict__ outB)
{
    __shared__ __align__(16) unsigned char smem[4 * 10240];

    const int tid  = threadIdx.x;
    const int wid  = tid >> 5;
    const int lane = tid & 31;
    const int warp_m = wid >> 2;     // 0..1
    const int warp_n = wid & 3;      // 0..3

    const int m0  = blockIdx.y * 128;
    const int nblk = blockIdx.x;
    const float* W    = (nblk < 2) ? Wf : Wb;
    const float* bias = (nblk < 2) ? bf : bb;
    float*       outp = (nblk < 2) ? outF : outB;
    const int n0 = (nblk & 1) * 128;

    const uint32_t sAhi = smem_u32(smem);
    const uint32_t sAlo = sAhi + 10240u;
    const uint32_t sWhi = sAhi + 20480u;
    const uint32_t sWlo = sAhi + 30720u;

    // staging: row = tid>>1 (0..127), half = tid&1 -> k cols [half*16, half*16+16)
    const int row  = tid >> 1;
    const int half = tid & 1;

    const float* arow;
    {
        int ma = m0 + row;
        if (MODE == 0)
            arow = A + ((size_t)(ma & 63) * SSQ + (size_t)(ma >> 6)) * II;
        else
            arow = A + (size_t)ma * K;
    }
    const float* wrow = W + (size_t)(n0 + row) * ldw;

    float acc[4][4][4];
#pragma unroll
    for (int mt = 0; mt < 4; mt++)
#pragma unroll
        for (int nt = 0; nt < 4; nt++)
#pragma unroll
            for (int q = 0; q < 4; q++) acc[mt][nt][q] = 0.0f;

    // prologue: prefetch chunk 0 (fp32) into registers
    float4 av[4], wv[4];
#pragma unroll
    for (int j = 0; j < 4; j++) {
        av[j] = *(const float4*)(arow + half * 16 + j * 4);
        wv[j] = *(const float4*)(wrow + half * 16 + j * 4);
    }

    const int NCH = K / 32;
#pragma unroll 1
    for (int ck = 0; ck < NCH; ck++) {
        __syncthreads();   // previous chunk's ldmatrix consumers done
        // convert + store staged chunk (SW-free padded layout)
#pragma unroll
        for (int j = 0; j < 4; j++) {
            uint32_t off = (uint32_t)(row * 80 + half * 32 + j * 8);
            uint32_t h01, h23, l01, l23;
            split_f4(av[j], h01, h23, l01, l23);
            sts_v2(sAhi + off, h01, h23);
            sts_v2(sAlo + off, l01, l23);
            split_f4(wv[j], h01, h23, l01, l23);
            sts_v2(sWhi + off, h01, h23);
            sts_v2(sWlo + off, l01, l23);
        }
        __syncthreads();

        // prefetch next chunk while MMAs run
        if (ck + 1 < NCH) {
            const int kb = (ck + 1) * 32 + half * 16;
#pragma unroll
            for (int j = 0; j < 4; j++) {
                av[j] = *(const float4*)(arow + kb + j * 4);
                wv[j] = *(const float4*)(wrow + kb + j * 4);
            }
        }

#pragma unroll
        for (int ks = 0; ks < 2; ks++) {
            uint32_t ahi[4][4], alo[4][4];
#pragma unroll
            for (int mt = 0; mt < 4; mt++) {
                uint32_t off = (uint32_t)((warp_m * 64 + mt * 16 + (lane & 15)) * 80
                                          + ks * 32 + ((lane >> 4) << 4));
                ldsm_x4(sAhi + off, ahi[mt][0], ahi[mt][1], ahi[mt][2], ahi[mt][3]);
                ldsm_x4(sAlo + off, alo[mt][0], alo[mt][1], alo[mt][2], alo[mt][3]);
            }
            uint32_t bhi[4][2], blo[4][2];
#pragma unroll
            for (int np = 0; np < 2; np++) {
                int nr = warp_n * 32 + np * 16 + (lane & 7) + ((lane & 16) >> 1);
                uint32_t off = (uint32_t)(nr * 80 + ks * 32 + ((lane >> 3) & 1) * 16);
                uint32_t r0, r1, r2, r3;
                ldsm_x4(sWhi + off, r0, r1, r2, r3);
                bhi[np * 2][0] = r0; bhi[np * 2][1] = r1;
                bhi[np * 2 + 1][0] = r2; bhi[np * 2 + 1][1] = r3;
                ldsm_x4(sWlo + off, r0, r1, r2, r3);
                blo[np * 2][0] = r0; blo[np * 2][1] = r1;
                blo[np * 2 + 1][0] = r2; blo[np * 2 + 1][1] = r3;
            }
#pragma unroll
            for (int mt = 0; mt < 4; mt++)
#pragma unroll
                for (int nt = 0; nt < 4; nt++)
                    mma16816(acc[mt][nt], ahi[mt], bhi[nt]);
#pragma unroll
            for (int mt = 0; mt < 4; mt++)
#pragma unroll
                for (int nt = 0; nt < 4; nt++)
                    mma16816(acc[mt][nt], ahi[mt], blo[nt]);
#pragma unroll
            for (int mt = 0; mt < 4; mt++)
#pragma unroll
                for (int nt = 0; nt < 4; nt++)
                    mma16816(acc[mt][nt], alo[mt], bhi[nt]);
        }
    }

    // epilogue: frag (m16n8): c0,c1 -> row lane/4, cols (lane&3)*2,+1; c2,c3 -> row+8
#pragma unroll
    for (int mt = 0; mt < 4; mt++) {
        const int mlo = m0 + warp_m * 64 + mt * 16 + (lane >> 2);
#pragma unroll
        for (int nt = 0; nt < 4; nt++) {
            const int n = n0 + warp_n * 32 + nt * 8 + (lane & 3) * 2;
            float2 bv = *(const float2*)(bias + n);
            float2 v0, v1;
            v0.x = acc[mt][nt][0] + bv.x;
            v0.y = acc[mt][nt][1] + bv.y;
            v1.x = acc[mt][nt][2] + bv.x;
            v1.y = acc[mt][nt][3] + bv.y;
            *(float2*)(outp + (size_t)mlo * 256 + n)       = v0;
            *(float2*)(outp + (size_t)(mlo + 8) * 256 + n) = v1;
        }
    }
}

// ---------------- batch-parallel recurrent scan (cluster of 2) ----------------
// 128 CTAs x 512 threads, clusters of 2. Cluster cl handles 2 recurrences:
// dir = cl>>5, batches bpair = (cl&31)*2 + {0,1}.
// CTA rank r owns output columns [r*128, r*128+128) and holds its half of Wh
// ENTIRELY IN REGISTERS. Per step: h(t-1) from SMEM, 128 FFMA/thread, shfl-reduce,
// exchange new half-h with peer via st.shared::cluster; arrive EARLY, then overlap
// global out-store + pre prefetch with the cluster barrier, then wait.
__global__ __launch_bounds__(512, 1) __cluster_dims__(2, 1, 1)
void scan2(const float* __restrict__ preF, const float* __restrict__ preB,
           const float* __restrict__ W_f, const float* __restrict__ W_b,
           int ldw, int whofs,
           float* __restrict__ out, size_t sS, size_t sB)
{
    __shared__ float hb[2 * 2 * 272];   // [parity][rec][272]

    const int tid = threadIdx.x;
    const int kq  = tid & 3;
    const int o   = tid >> 2;          // 0..127
    uint32_t r;
    asm("mov.u32 %0, %%cluster_ctarank;" : "=r"(r));
    const int cl    = blockIdx.x >> 1;
    const int dir   = cl >> 5;
    const int bpair = (cl & 31) * 2;
    const int colg  = (int)r * 128 + o;

    const float* pre = dir ? preB : preF;
    const float* W   = dir ? W_b : W_f;

    // load my 64 weights into registers (once)
    float4 wreg[16];
    {
        const float* wp = W + (size_t)colg * ldw + whofs + kq * 64;
#pragma unroll
        for (int i = 0; i < 16; i++) wreg[i] = *(const float4*)(wp + i * 4);
    }

    const bool active = (kq < 2);          // lanes that own a (rec, col) output
    const int  myb    = bpair + kq;        // batch for my rec (valid if active)

    uint32_t hb_base;
    asm("{ .reg .u64 t; cvta.to.shared.u64 t, %1; cvt.u32.u64 %0, t; }"
        : "=r"(hb_base) : "l"(hb));

    // precompute peer address for my h slot (both parities)
    const int hidx0 = 0 * 544 + kq * 272 + (colg >> 6) * 68 + (colg & 63);
    uint32_t raddr0 = 0;
    if (active) {
        uint32_t laddr = hb_base + (uint32_t)hidx0 * 4u;
        asm("mapa.shared::cluster.u32 %0, %1, %2;"
            : "=r"(raddr0) : "r"(laddr), "r"(r ^ 1u));
    }

    int s = dir ? 2047 : 0;
    const int sstep = dir ? -1 : 1;

    float pval = 0.f;
    if (active) pval = __ldg(pre + ((size_t)s * 64 + myb) * 256 + colg);

    float* outp = out + (size_t)myb * sB + (size_t)dir * 256 + colg;

    int par = 0;
    for (int t = 0; t < 2048; ++t) {
        float sum0 = 0.f, sum1 = 0.f;
        if (t > 0) {
            float a00 = 0.f, a01 = 0.f, a02 = 0.f, a03 = 0.f;
            float a10 = 0.f, a11 = 0.f, a12 = 0.f, a13 = 0.f;
            const float* h0 = &hb[par * 544 + 0 * 272 + kq * 68];
            const float* h1 = &hb[par * 544 + 1 * 272 + kq * 68];
#pragma unroll
            for (int i = 0; i < 16; i++) {
                float4 h = *(const float4*)(h0 + i * 4);
                a00 = fmaf(wreg[i].x, h.x, a00);
                a01 = fmaf(wreg[i].y, h.y, a01);
                a02 = fmaf(wreg[i].z, h.z, a02);
                a03 = fmaf(wreg[i].w, h.w, a03);
            }
#pragma unroll
            for (int i = 0; i < 16; i++) {
                float4 h = *(const float4*)(h1 + i * 4);
                a10 = fmaf(wreg[i].x, h.x, a10);
                a11 = fmaf(wreg[i].y, h.y, a11);
                a12 = fmaf(wreg[i].z, h.z, a12);
                a13 = fmaf(wreg[i].w, h.w, a13);
            }
            sum0 = (a00 + a01) + (a02 + a03);
            sum1 = (a10 + a11) + (a12 + a13);
            // reduce over the 4 kq lanes (lane bits 0,1)
            sum0 += __shfl_xor_sync(0xffffffffu, sum0, 1);
            sum0 += __shfl_xor_sync(0xffffffffu, sum0, 2);
            sum1 += __shfl_xor_sync(0xffffffffu, sum1, 1);
            sum1 += __shfl_xor_sync(0xffffffffu, sum1, 2);
        }

        float hnew = 0.f;
        if (active) {
            float acc = (kq == 0) ? sum0 : sum1;
            hnew = tanhf(pval + acc);
        }

        if (t < 2047) {
            const int np = par ^ 1;
            if (active) {
                const int hidx = np * 544 + hidx0;
                hb[hidx] = hnew;                        // own buffer
                uint32_t raddr = raddr0 + (uint32_t)(np * 544) * 4u;
                asm volatile("st.shared::cluster.f32 [%0], %1;"
                             :: "r"(raddr), "f"(hnew) : "memory");
            }
            // release: prior (cluster-)shared stores visible to peer after its wait
            asm volatile("barrier.cluster.arrive.aligned;" ::: "memory");

            // overlap with barrier: global out store + next pre prefetch
            if (active) __stcg(outp + (size_t)s * sS, hnew);
            s += sstep;
            if (active) pval = __ldg(pre + ((size_t)s * 64 + myb) * 256 + colg);

            asm volatile("barrier.cluster.wait.aligned;" ::: "memory");
            par = np;
        } else {
            if (active) __stcg(outp + (size_t)s * sS, hnew);
        }
    }
}

// ---------------- launch ----------------
extern "C" void kernel_launch(void* const* d_in, const int* in_sizes, int n_in,
                              void* d_out, int out_size) {
    const float* x   = (const float*)d_in[0];
    const float* W0f = (const float*)d_in[1];
    const float* b0f = (const float*)d_in[2];
    const float* W0b = (const float*)d_in[3];
    const float* b0b = (const float*)d_in[4];
    const float* W1f = (const float*)d_in[5];
    const float* b1f = (const float*)d_in[6];
    const float* W1b = (const float*)d_in[7];
    const float* b1b = (const float*)d_in[8];
    float* out = (float*)d_out;

    float *preF, *preB, *y0;
    cudaGetSymbolAddress((void**)&preF, g_preA);
    cudaGetSymbolAddress((void**)&preB, g_preB);
    cudaGetSymbolAddress((void**)&y0,   g_y0);

    const size_t OUT_ELEMS = (size_t)BB * SSQ * 2 * HH;   // 67108864
    const int HN_ELEMS = 4 * BB * HH;                     // 65536

    // zero hn
    init_kernel<<<256, 256>>>(out + OUT_ELEMS, HN_ELEMS);

    // layer 0: pre = x @ Wx^T + b  (K=256, Wx = W0*[:, 0:256], ldw=512)
    gemm_pre_mma<256, 0><<<dim3(4, 1024), 256>>>(
        x, W0f, W0b, b0f, b0b, 512, preF, preB);

    // layer 0 scan -> y0 [s][b][512] (fwd cols 0:256, bwd 256:512)
    scan2<<<128, 512>>>(preF, preB, W0f, W0b, 512, 256,
                        y0, (size_t)BB * 512, (size_t)512);

    // layer 1: pre = y0 @ Wx^T + b  (K=512, Wx = W1*[:, 0:512], ldw=768)
    gemm_pre_mma<512, 1><<<dim3(4, 1024), 256>>>(
        y0, W1f, W1b, b1f, b1b, 768, preF, preB);

    // layer 1 scan -> out[b][s][512]
    scan2<<<128, 512>>>(preF, preB, W1f, W1b, 768, 512,
                        out, (size_t)512, (size_t)SSQ * 512);
}